// round 4
// baseline (speedup 1.0000x reference)
#include <cuda_runtime.h>

// GRU: B=4096, T=512, I=32, H=64. out = final hidden (B, H) fp32.
// 128 CTAs x 256 threads. Split-k: warps 0-3 (one per SMSP) do k=[0,48),
// warps 4-7 do k=[48,96) for the SAME 32 batch rows -> 2 warps/SMSP for
// latency hiding WITHOUT duplicating weight smem traffic. Partials exchanged
// via smem scratch; epilogue split (w: rows 0-3, w+4: rows 4-7).
// GEMM path: packed fma.rn.f32x2; A operands stored duplicated in smem.

#define THREADS      256
#define ROWS_PER_CTA 32
#define RPW          8       // rows per warp tile (full tile; epilogue splits 4/4)
#define I_DIM        32
#define H_DIM        64
#define G_DIM        192
#define S_DUP        68      // duplicated-A row stride (floats), 272B

#define WS_FLOATS    (96 * G_DIM)         // 18432
#define HD_FLOATS    (H_DIM * S_DUP)      // 4352
#define XD_FLOATS    (I_DIM * S_DUP)      // 2176
#define SC_U64       (4 * 8 * 4 * 32)     // smsp x row x acc x lane = 4096 u64
#define SMEM_BYTES   ((WS_FLOATS + HD_FLOATS + XD_FLOATS) * 4 + SC_U64 * 8)

typedef unsigned long long u64;

__device__ __forceinline__ void fma2(u64& d, u64 a, u64 b) {
    asm("fma.rn.f32x2 %0, %1, %2, %0;" : "+l"(d) : "l"(a), "l"(b));
}
__device__ __forceinline__ u64 add2(u64 a, u64 b) {
    u64 r;
    asm("add.rn.f32x2 %0, %1, %2;" : "=l"(r) : "l"(a), "l"(b));
    return r;
}
__device__ __forceinline__ float2 upk(u64 v) {
    float2 f;
    asm("mov.b64 {%0, %1}, %2;" : "=f"(f.x), "=f"(f.y) : "l"(v));
    return f;
}
__device__ __forceinline__ float tanh_hw(float x) {      // r,z gates
    float y;
    asm("tanh.approx.f32 %0, %1;" : "=f"(y) : "f"(x));
    return y;
}
__device__ __forceinline__ float sig_hw(float x) {
    return fmaf(tanh_hw(0.5f * x), 0.5f, 0.5f);
}
__device__ __forceinline__ float tanh_acc(float x) {     // n gate (accurate)
    return __fdividef(2.0f, 1.0f + __expf(-2.0f * x)) - 1.0f;
}

__global__ void __launch_bounds__(THREADS, 1)
gru_fwd_kernel(const float* __restrict__ seq,
               const float* __restrict__ W_ih,
               const float* __restrict__ W_hh,
               const float* __restrict__ b_ih,
               const float* __restrict__ b_hh,
               float* __restrict__ out,
               int B, int T)
{
    extern __shared__ float sm[];
    float* Ws = sm;                        // Ws[k][g]
    float* HD = sm + WS_FLOATS;            // HD[k][2*row] duplicated h
    float* XD = HD + HD_FLOATS;            // XD[k][2*row] duplicated x_t
    u64*   SC = (u64*)(XD + XD_FLOATS);    // partial-sum exchange

    const int tid   = threadIdx.x;
    const int w     = tid >> 5;
    const int c     = tid & 31;
    const int grp   = w >> 2;              // 0: k=[0,48)  1: k=[48,96)
    const int smsp  = w & 3;
    const int bb    = blockIdx.x * ROWS_PER_CTA;
    const int r0    = smsp * RPW;          // rows r0..r0+7
    const int j0    = 2 * c;               // output pair {j0, j0+1}

    // ---- one-time weight transpose into smem ----
    for (int idx = tid; idx < G_DIM * H_DIM; idx += THREADS) {
        int gg = idx / H_DIM, k = idx % H_DIM;
        Ws[k * G_DIM + gg] = W_hh[idx];
    }
    for (int idx = tid; idx < G_DIM * I_DIM; idx += THREADS) {
        int gg = idx / I_DIM, i = idx % I_DIM;
        Ws[(H_DIM + i) * G_DIM + gg] = W_ih[idx];
    }
    for (int idx = tid; idx < HD_FLOATS; idx += THREADS) HD[idx] = 0.0f;

    // ---- biases for this lane's pair ----
    const float bR0  = b_ih[j0]      + b_hh[j0];
    const float bR1  = b_ih[j0 + 1]  + b_hh[j0 + 1];
    const float bZ0  = b_ih[64 + j0] + b_hh[64 + j0];
    const float bZ1  = b_ih[65 + j0] + b_hh[65 + j0];
    const float bIN0 = b_ih[128 + j0], bIN1 = b_ih[129 + j0];
    const float bHN0 = b_hh[128 + j0], bHN1 = b_hh[129 + j0];

    // ---- x loader role: 8 threads per batch row, float4 each ----
    const int xrow = tid >> 3;             // 0..31
    const int xc4  = (tid & 7) * 4;        // 0,4,...,28
    const float* xptr = seq + (size_t)(bb + xrow) * T * I_DIM + xc4;

    // epilogue rows for this warp: lbase..lbase+3 (local), hreg holds them
    const int lbase = grp ? 4 : 0;
    float hreg[4][2];
    #pragma unroll
    for (int i = 0; i < 4; ++i) { hreg[i][0] = 0.0f; hreg[i][1] = 0.0f; }

    // stage x(0) duplicated
    {
        float4 xv = *reinterpret_cast<const float4*>(xptr);
        float v[4] = {xv.x, xv.y, xv.z, xv.w};
        #pragma unroll
        for (int i = 0; i < 4; ++i)
            *reinterpret_cast<float2*>(&XD[(xc4 + i) * S_DUP + 2 * xrow]) =
                make_float2(v[i], v[i]);
    }
    __syncthreads();

    for (int t = 0; t < T; ++t) {
        // prefetch x(t+1) under the GEMM
        float4 xn4 = make_float4(0.f, 0.f, 0.f, 0.f);
        if (t + 1 < T)
            xn4 = *reinterpret_cast<const float4*>(xptr + (size_t)(t + 1) * I_DIM);

        u64 aR[RPW], aZ[RPW], aN[RPW], aX[RPW];
        #pragma unroll
        for (int i = 0; i < RPW; ++i) { aR[i] = 0; aZ[i] = 0; aN[i] = 0; aX[i] = 0; }

        if (grp == 0) {
            // ---- k = 0..47 over HD (r, z, hn) ----
            #pragma unroll 8
            for (int k = 0; k < 48; ++k) {
                const float* hk = &HD[k * S_DUP + 2 * r0];
                ulonglong2 A0 = *reinterpret_cast<const ulonglong2*>(hk);
                ulonglong2 A1 = *reinterpret_cast<const ulonglong2*>(hk + 4);
                ulonglong2 A2 = *reinterpret_cast<const ulonglong2*>(hk + 8);
                ulonglong2 A3 = *reinterpret_cast<const ulonglong2*>(hk + 12);
                const float* wk = &Ws[k * G_DIM + j0];
                u64 wr = *reinterpret_cast<const u64*>(wk);
                u64 wz = *reinterpret_cast<const u64*>(wk + 64);
                u64 wn = *reinterpret_cast<const u64*>(wk + 128);
                fma2(aR[0], A0.x, wr); fma2(aR[1], A0.y, wr);
                fma2(aR[2], A1.x, wr); fma2(aR[3], A1.y, wr);
                fma2(aR[4], A2.x, wr); fma2(aR[5], A2.y, wr);
                fma2(aR[6], A3.x, wr); fma2(aR[7], A3.y, wr);
                fma2(aZ[0], A0.x, wz); fma2(aZ[1], A0.y, wz);
                fma2(aZ[2], A1.x, wz); fma2(aZ[3], A1.y, wz);
                fma2(aZ[4], A2.x, wz); fma2(aZ[5], A2.y, wz);
                fma2(aZ[6], A3.x, wz); fma2(aZ[7], A3.y, wz);
                fma2(aN[0], A0.x, wn); fma2(aN[1], A0.y, wn);
                fma2(aN[2], A1.x, wn); fma2(aN[3], A1.y, wn);
                fma2(aN[4], A2.x, wn); fma2(aN[5], A2.y, wn);
                fma2(aN[6], A3.x, wn); fma2(aN[7], A3.y, wn);
            }
        } else {
            // ---- k = 48..63 over HD (r, z, hn) ----
            #pragma unroll 8
            for (int k = 48; k < 64; ++k) {
                const float* hk = &HD[k * S_DUP + 2 * r0];
                ulonglong2 A0 = *reinterpret_cast<const ulonglong2*>(hk);
                ulonglong2 A1 = *reinterpret_cast<const ulonglong2*>(hk + 4);
                ulonglong2 A2 = *reinterpret_cast<const ulonglong2*>(hk + 8);
                ulonglong2 A3 = *reinterpret_cast<const ulonglong2*>(hk + 12);
                const float* wk = &Ws[k * G_DIM + j0];
                u64 wr = *reinterpret_cast<const u64*>(wk);
                u64 wz = *reinterpret_cast<const u64*>(wk + 64);
                u64 wn = *reinterpret_cast<const u64*>(wk + 128);
                fma2(aR[0], A0.x, wr); fma2(aR[1], A0.y, wr);
                fma2(aR[2], A1.x, wr); fma2(aR[3], A1.y, wr);
                fma2(aR[4], A2.x, wr); fma2(aR[5], A2.y, wr);
                fma2(aR[6], A3.x, wr); fma2(aR[7], A3.y, wr);
                fma2(aZ[0], A0.x, wz); fma2(aZ[1], A0.y, wz);
                fma2(aZ[2], A1.x, wz); fma2(aZ[3], A1.y, wz);
                fma2(aZ[4], A2.x, wz); fma2(aZ[5], A2.y, wz);
                fma2(aZ[6], A3.x, wz); fma2(aZ[7], A3.y, wz);
                fma2(aN[0], A0.x, wn); fma2(aN[1], A0.y, wn);
                fma2(aN[2], A1.x, wn); fma2(aN[3], A1.y, wn);
                fma2(aN[4], A2.x, wn); fma2(aN[5], A2.y, wn);
                fma2(aN[6], A3.x, wn); fma2(aN[7], A3.y, wn);
            }
            // ---- k = 0..31 over XD (r, z, xn) ----
            #pragma unroll 8
            for (int k = 0; k < I_DIM; ++k) {
                const float* xk = &XD[k * S_DUP + 2 * r0];
                ulonglong2 A0 = *reinterpret_cast<const ulonglong2*>(xk);
                ulonglong2 A1 = *reinterpret_cast<const ulonglong2*>(xk + 4);
                ulonglong2 A2 = *reinterpret_cast<const ulonglong2*>(xk + 8);
                ulonglong2 A3 = *reinterpret_cast<const ulonglong2*>(xk + 12);
                const float* wk = &Ws[(H_DIM + k) * G_DIM + j0];
                u64 wr = *reinterpret_cast<const u64*>(wk);
                u64 wz = *reinterpret_cast<const u64*>(wk + 64);
                u64 wn = *reinterpret_cast<const u64*>(wk + 128);
                fma2(aR[0], A0.x, wr); fma2(aR[1], A0.y, wr);
                fma2(aR[2], A1.x, wr); fma2(aR[3], A1.y, wr);
                fma2(aR[4], A2.x, wr); fma2(aR[5], A2.y, wr);
                fma2(aR[6], A3.x, wr); fma2(aR[7], A3.y, wr);
                fma2(aZ[0], A0.x, wz); fma2(aZ[1], A0.y, wz);
                fma2(aZ[2], A1.x, wz); fma2(aZ[3], A1.y, wz);
                fma2(aZ[4], A2.x, wz); fma2(aZ[5], A2.y, wz);
                fma2(aZ[6], A3.x, wz); fma2(aZ[7], A3.y, wz);
                fma2(aX[0], A0.x, wn); fma2(aX[1], A0.y, wn);
                fma2(aX[2], A1.x, wn); fma2(aX[3], A1.y, wn);
                fma2(aX[4], A2.x, wn); fma2(aX[5], A2.y, wn);
                fma2(aX[6], A3.x, wn); fma2(aX[7], A3.y, wn);
            }
        }

        // ---- ship partials for the rows the partner warp will finish ----
        // slot(l, a) for this smsp, lane c
        #define SLOT(l, a) ((((smsp) * 8 + (l)) * 4 + (a)) * 32 + c)
        if (grp == 0) {
            #pragma unroll
            for (int l = 4; l < 8; ++l) {
                SC[SLOT(l, 0)] = aR[l];
                SC[SLOT(l, 1)] = aZ[l];
                SC[SLOT(l, 2)] = aN[l];
            }
        } else {
            #pragma unroll
            for (int l = 0; l < 4; ++l) {
                SC[SLOT(l, 0)] = aR[l];
                SC[SLOT(l, 1)] = aZ[l];
                SC[SLOT(l, 2)] = aN[l];
                SC[SLOT(l, 3)] = aX[l];
            }
        }
        __syncthreads();   // drains STS; all HD/XD reads for step t done

        // stage x(t+1) duplicated (all threads)
        if (t + 1 < T) {
            float v[4] = {xn4.x, xn4.y, xn4.z, xn4.w};
            #pragma unroll
            for (int i = 0; i < 4; ++i)
                *reinterpret_cast<float2*>(&XD[(xc4 + i) * S_DUP + 2 * xrow]) =
                    make_float2(v[i], v[i]);
        }

        // ---- reduce + gate epilogue for this warp's 4 rows ----
        #pragma unroll
        for (int i = 0; i < 4; ++i) {
            const int l = lbase + i;
            u64 sR = add2(aR[l], SC[SLOT(l, 0)]);
            u64 sZ = add2(aZ[l], SC[SLOT(l, 1)]);
            u64 sN = add2(aN[l], SC[SLOT(l, 2)]);
            u64 sX = grp ? aX[l] : SC[SLOT(l, 3)];
            float2 uR = upk(sR);
            float2 uZ = upk(sZ);
            float2 uH = upk(sN);
            float2 uX = upk(sX);
            float r0g = sig_hw(uR.x + bR0);
            float z0g = sig_hw(uZ.x + bZ0);
            float n0  = tanh_acc(uX.x + bIN0 + r0g * (uH.x + bHN0));
            float h0  = n0 + z0g * (hreg[i][0] - n0);
            float r1g = sig_hw(uR.y + bR1);
            float z1g = sig_hw(uZ.y + bZ1);
            float n1  = tanh_acc(uX.y + bIN1 + r1g * (uH.y + bHN1));
            float h1  = n1 + z1g * (hreg[i][1] - n1);
            hreg[i][0] = h0;
            hreg[i][1] = h1;
            const int gr = r0 + l;
            *reinterpret_cast<float2*>(&HD[j0 * S_DUP + 2 * gr])       = make_float2(h0, h0);
            *reinterpret_cast<float2*>(&HD[(j0 + 1) * S_DUP + 2 * gr]) = make_float2(h1, h1);
        }
        __syncthreads();   // HD/XD ready for step t+1
        #undef SLOT
    }

    // ---- final output: each warp writes its 4 epilogue rows ----
    #pragma unroll
    for (int i = 0; i < 4; ++i) {
        int b = bb + r0 + lbase + i;
        if (b < B)
            *reinterpret_cast<float2*>(&out[(size_t)b * H_DIM + j0]) =
                make_float2(hreg[i][0], hreg[i][1]);
    }
}

extern "C" void kernel_launch(void* const* d_in, const int* in_sizes, int n_in,
                              void* d_out, int out_size) {
    const float* seq  = (const float*)d_in[0];
    const float* W_ih = (const float*)d_in[1];
    const float* W_hh = (const float*)d_in[2];
    const float* b_ih = (const float*)d_in[3];
    const float* b_hh = (const float*)d_in[4];
    float* out = (float*)d_out;

    const int B = out_size / H_DIM;              // 4096
    const int T = in_sizes[0] / (B * I_DIM);     // 512

    cudaFuncSetAttribute(gru_fwd_kernel,
                         cudaFuncAttributeMaxDynamicSharedMemorySize, SMEM_BYTES);

    const int grid = (B + ROWS_PER_CTA - 1) / ROWS_PER_CTA;  // 128
    gru_fwd_kernel<<<grid, THREADS, SMEM_BYTES>>>(seq, W_ih, W_hh, b_ih, b_hh,
                                                  out, B, T);
}

// round 5
// speedup vs baseline: 1.3952x; 1.3952x over previous
#include <cuda_runtime.h>

// GRU: B=4096, T=512, I=32, H=64. out = final hidden (B, H) fp32.
// 128 CTAs x 256 threads. Split-k: warps 0-3 (one per SMSP) do k=[0,48),
// warps 4-7 do k=[48,96) for the SAME 32 batch rows -> 2 warps/SMSP for
// latency hiding WITHOUT duplicating weight smem traffic. Partials exchanged
// via smem scratch; epilogue split (grp0: rows 0-3, grp1: rows 4-7) with
// COMPILE-TIME accumulator indices only (dynamic indexing spills to local).

#define THREADS      256
#define ROWS_PER_CTA 32
#define RPW          8
#define I_DIM        32
#define H_DIM        64
#define G_DIM        192
#define S_DUP        68      // duplicated-A row stride (floats), 272B

#define WS_FLOATS    (96 * G_DIM)         // 18432
#define HD_FLOATS    (H_DIM * S_DUP)      // 4352
#define XD_FLOATS    (I_DIM * S_DUP)      // 2176
#define SC_U64       (4 * 8 * 4 * 32)     // smsp x row x acc x lane
#define SMEM_BYTES   ((WS_FLOATS + HD_FLOATS + XD_FLOATS) * 4 + SC_U64 * 8)

typedef unsigned long long u64;

__device__ __forceinline__ void fma2(u64& d, u64 a, u64 b) {
    asm("fma.rn.f32x2 %0, %1, %2, %0;" : "+l"(d) : "l"(a), "l"(b));
}
__device__ __forceinline__ u64 add2(u64 a, u64 b) {
    u64 r;
    asm("add.rn.f32x2 %0, %1, %2;" : "=l"(r) : "l"(a), "l"(b));
    return r;
}
__device__ __forceinline__ float2 upk(u64 v) {
    float2 f;
    asm("mov.b64 {%0, %1}, %2;" : "=f"(f.x), "=f"(f.y) : "l"(v));
    return f;
}
__device__ __forceinline__ float tanh_hw(float x) {
    float y;
    asm("tanh.approx.f32 %0, %1;" : "=f"(y) : "f"(x));
    return y;
}
__device__ __forceinline__ float sig_hw(float x) {
    return fmaf(tanh_hw(0.5f * x), 0.5f, 0.5f);
}
__device__ __forceinline__ float tanh_acc(float x) {
    return __fdividef(2.0f, 1.0f + __expf(-2.0f * x)) - 1.0f;
}

struct GateB { float bR0, bR1, bZ0, bZ1, bIN0, bIN1, bHN0, bHN1; };

// One row's gate math; h01 updated in place. All inputs packed u64 pairs.
__device__ __forceinline__ void gate_row(u64 sR, u64 sZ, u64 sN, u64 sX,
                                         const GateB& b, float2& h01) {
    float2 uR = upk(sR), uZ = upk(sZ), uH = upk(sN), uX = upk(sX);
    float r0g = sig_hw(uR.x + b.bR0);
    float z0g = sig_hw(uZ.x + b.bZ0);
    float n0  = tanh_acc(uX.x + b.bIN0 + r0g * (uH.x + b.bHN0));
    float r1g = sig_hw(uR.y + b.bR1);
    float z1g = sig_hw(uZ.y + b.bZ1);
    float n1  = tanh_acc(uX.y + b.bIN1 + r1g * (uH.y + b.bHN1));
    h01.x = n0 + z0g * (h01.x - n0);
    h01.y = n1 + z1g * (h01.y - n1);
}

#define KSTEP_HN(k)                                                          \
    {                                                                        \
        const float* hk = &HD[(k) * S_DUP + 2 * r0];                         \
        ulonglong2 A0 = *reinterpret_cast<const ulonglong2*>(hk);            \
        ulonglong2 A1 = *reinterpret_cast<const ulonglong2*>(hk + 4);        \
        ulonglong2 A2 = *reinterpret_cast<const ulonglong2*>(hk + 8);        \
        ulonglong2 A3 = *reinterpret_cast<const ulonglong2*>(hk + 12);       \
        const float* wk = &Ws[(k) * G_DIM + j0];                             \
        u64 wr = *reinterpret_cast<const u64*>(wk);                          \
        u64 wz = *reinterpret_cast<const u64*>(wk + 64);                     \
        u64 wn = *reinterpret_cast<const u64*>(wk + 128);                    \
        fma2(aR[0], A0.x, wr); fma2(aR[1], A0.y, wr);                        \
        fma2(aR[2], A1.x, wr); fma2(aR[3], A1.y, wr);                        \
        fma2(aR[4], A2.x, wr); fma2(aR[5], A2.y, wr);                        \
        fma2(aR[6], A3.x, wr); fma2(aR[7], A3.y, wr);                        \
        fma2(aZ[0], A0.x, wz); fma2(aZ[1], A0.y, wz);                        \
        fma2(aZ[2], A1.x, wz); fma2(aZ[3], A1.y, wz);                        \
        fma2(aZ[4], A2.x, wz); fma2(aZ[5], A2.y, wz);                        \
        fma2(aZ[6], A3.x, wz); fma2(aZ[7], A3.y, wz);                        \
        fma2(aN[0], A0.x, wn); fma2(aN[1], A0.y, wn);                        \
        fma2(aN[2], A1.x, wn); fma2(aN[3], A1.y, wn);                        \
        fma2(aN[4], A2.x, wn); fma2(aN[5], A2.y, wn);                        \
        fma2(aN[6], A3.x, wn); fma2(aN[7], A3.y, wn);                        \
    }

#define KSTEP_X(k)                                                           \
    {                                                                        \
        const float* xk = &XD[(k) * S_DUP + 2 * r0];                         \
        ulonglong2 A0 = *reinterpret_cast<const ulonglong2*>(xk);            \
        ulonglong2 A1 = *reinterpret_cast<const ulonglong2*>(xk + 4);        \
        ulonglong2 A2 = *reinterpret_cast<const ulonglong2*>(xk + 8);        \
        ulonglong2 A3 = *reinterpret_cast<const ulonglong2*>(xk + 12);       \
        const float* wk = &Ws[(H_DIM + (k)) * G_DIM + j0];                   \
        u64 wr = *reinterpret_cast<const u64*>(wk);                          \
        u64 wz = *reinterpret_cast<const u64*>(wk + 64);                     \
        u64 wn = *reinterpret_cast<const u64*>(wk + 128);                    \
        fma2(aR[0], A0.x, wr); fma2(aR[1], A0.y, wr);                        \
        fma2(aR[2], A1.x, wr); fma2(aR[3], A1.y, wr);                        \
        fma2(aR[4], A2.x, wr); fma2(aR[5], A2.y, wr);                        \
        fma2(aR[6], A3.x, wr); fma2(aR[7], A3.y, wr);                        \
        fma2(aZ[0], A0.x, wz); fma2(aZ[1], A0.y, wz);                        \
        fma2(aZ[2], A1.x, wz); fma2(aZ[3], A1.y, wz);                        \
        fma2(aZ[4], A2.x, wz); fma2(aZ[5], A2.y, wz);                        \
        fma2(aZ[6], A3.x, wz); fma2(aZ[7], A3.y, wz);                        \
        fma2(aX[0], A0.x, wn); fma2(aX[1], A0.y, wn);                        \
        fma2(aX[2], A1.x, wn); fma2(aX[3], A1.y, wn);                        \
        fma2(aX[4], A2.x, wn); fma2(aX[5], A2.y, wn);                        \
        fma2(aX[6], A3.x, wn); fma2(aX[7], A3.y, wn);                        \
    }

__global__ void __launch_bounds__(THREADS, 1)
gru_fwd_kernel(const float* __restrict__ seq,
               const float* __restrict__ W_ih,
               const float* __restrict__ W_hh,
               const float* __restrict__ b_ih,
               const float* __restrict__ b_hh,
               float* __restrict__ out,
               int B, int T)
{
    extern __shared__ float sm[];
    float* Ws = sm;
    float* HD = sm + WS_FLOATS;
    float* XD = HD + HD_FLOATS;
    u64*   SC = (u64*)(XD + XD_FLOATS);

    const int tid  = threadIdx.x;
    const int w    = tid >> 5;
    const int c    = tid & 31;
    const int grp  = w >> 2;               // 0: k=[0,48)  1: k=[48,96)
    const int smsp = w & 3;
    const int bb   = blockIdx.x * ROWS_PER_CTA;
    const int r0   = smsp * RPW;
    const int j0   = 2 * c;

    for (int idx = tid; idx < G_DIM * H_DIM; idx += THREADS) {
        int gg = idx / H_DIM, k = idx % H_DIM;
        Ws[k * G_DIM + gg] = W_hh[idx];
    }
    for (int idx = tid; idx < G_DIM * I_DIM; idx += THREADS) {
        int gg = idx / I_DIM, i = idx % I_DIM;
        Ws[(H_DIM + i) * G_DIM + gg] = W_ih[idx];
    }
    for (int idx = tid; idx < HD_FLOATS; idx += THREADS) HD[idx] = 0.0f;

    GateB gb;
    gb.bR0  = b_ih[j0]      + b_hh[j0];
    gb.bR1  = b_ih[j0 + 1]  + b_hh[j0 + 1];
    gb.bZ0  = b_ih[64 + j0] + b_hh[64 + j0];
    gb.bZ1  = b_ih[65 + j0] + b_hh[65 + j0];
    gb.bIN0 = b_ih[128 + j0]; gb.bIN1 = b_ih[129 + j0];
    gb.bHN0 = b_hh[128 + j0]; gb.bHN1 = b_hh[129 + j0];

    const int xrow = tid >> 3;
    const int xc4  = (tid & 7) * 4;
    const float* xptr = seq + (size_t)(bb + xrow) * T * I_DIM + xc4;

    float2 h0r = make_float2(0.f, 0.f), h1r = h0r, h2r = h0r, h3r = h0r;

    {
        float4 xv = *reinterpret_cast<const float4*>(xptr);
        float v[4] = {xv.x, xv.y, xv.z, xv.w};
        #pragma unroll
        for (int i = 0; i < 4; ++i)
            *reinterpret_cast<float2*>(&XD[(xc4 + i) * S_DUP + 2 * xrow]) =
                make_float2(v[i], v[i]);
    }
    __syncthreads();

    #define SLOT(l, a) ((((smsp) * 8 + (l)) * 4 + (a)) * 32 + c)

    for (int t = 0; t < T; ++t) {
        float4 xn4 = make_float4(0.f, 0.f, 0.f, 0.f);
        if (t + 1 < T)
            xn4 = *reinterpret_cast<const float4*>(xptr + (size_t)(t + 1) * I_DIM);

        if (grp == 0) {
            u64 aR[RPW], aZ[RPW], aN[RPW];
            #pragma unroll
            for (int i = 0; i < RPW; ++i) { aR[i] = 0; aZ[i] = 0; aN[i] = 0; }
            #pragma unroll 8
            for (int k = 0; k < 48; ++k) KSTEP_HN(k)

            // ship rows 4-7 partials (r,z,hn)
            #pragma unroll
            for (int l = 4; l < 8; ++l) {
                SC[SLOT(l, 0)] = aR[l];
                SC[SLOT(l, 1)] = aZ[l];
                SC[SLOT(l, 2)] = aN[l];
            }
            __syncthreads();

            if (t + 1 < T) {
                float v[4] = {xn4.x, xn4.y, xn4.z, xn4.w};
                #pragma unroll
                for (int i = 0; i < 4; ++i)
                    *reinterpret_cast<float2*>(&XD[(xc4 + i) * S_DUP + 2 * xrow]) =
                        make_float2(v[i], v[i]);
            }

            // finish rows 0-3: constant indices only
            gate_row(add2(aR[0], SC[SLOT(0, 0)]), add2(aZ[0], SC[SLOT(0, 1)]),
                     add2(aN[0], SC[SLOT(0, 2)]), SC[SLOT(0, 3)], gb, h0r);
            gate_row(add2(aR[1], SC[SLOT(1, 0)]), add2(aZ[1], SC[SLOT(1, 1)]),
                     add2(aN[1], SC[SLOT(1, 2)]), SC[SLOT(1, 3)], gb, h1r);
            gate_row(add2(aR[2], SC[SLOT(2, 0)]), add2(aZ[2], SC[SLOT(2, 1)]),
                     add2(aN[2], SC[SLOT(2, 2)]), SC[SLOT(2, 3)], gb, h2r);
            gate_row(add2(aR[3], SC[SLOT(3, 0)]), add2(aZ[3], SC[SLOT(3, 1)]),
                     add2(aN[3], SC[SLOT(3, 2)]), SC[SLOT(3, 3)], gb, h3r);

            *reinterpret_cast<float2*>(&HD[j0 * S_DUP + 2 * (r0 + 0)])       = make_float2(h0r.x, h0r.x);
            *reinterpret_cast<float2*>(&HD[(j0 + 1) * S_DUP + 2 * (r0 + 0)]) = make_float2(h0r.y, h0r.y);
            *reinterpret_cast<float2*>(&HD[j0 * S_DUP + 2 * (r0 + 1)])       = make_float2(h1r.x, h1r.x);
            *reinterpret_cast<float2*>(&HD[(j0 + 1) * S_DUP + 2 * (r0 + 1)]) = make_float2(h1r.y, h1r.y);
            *reinterpret_cast<float2*>(&HD[j0 * S_DUP + 2 * (r0 + 2)])       = make_float2(h2r.x, h2r.x);
            *reinterpret_cast<float2*>(&HD[(j0 + 1) * S_DUP + 2 * (r0 + 2)]) = make_float2(h2r.y, h2r.y);
            *reinterpret_cast<float2*>(&HD[j0 * S_DUP + 2 * (r0 + 3)])       = make_float2(h3r.x, h3r.x);
            *reinterpret_cast<float2*>(&HD[(j0 + 1) * S_DUP + 2 * (r0 + 3)]) = make_float2(h3r.y, h3r.y);
        } else {
            u64 aR[RPW], aZ[RPW], aN[RPW], aX[RPW];
            #pragma unroll
            for (int i = 0; i < RPW; ++i) { aR[i] = 0; aZ[i] = 0; aN[i] = 0; aX[i] = 0; }
            #pragma unroll 8
            for (int k = 48; k < 64; ++k) KSTEP_HN(k)
            #pragma unroll 8
            for (int k = 0; k < I_DIM; ++k) KSTEP_X(k)

            // ship rows 0-3 partials (r,z,hn,xn)
            #pragma unroll
            for (int l = 0; l < 4; ++l) {
                SC[SLOT(l, 0)] = aR[l];
                SC[SLOT(l, 1)] = aZ[l];
                SC[SLOT(l, 2)] = aN[l];
                SC[SLOT(l, 3)] = aX[l];
            }
            __syncthreads();

            if (t + 1 < T) {
                float v[4] = {xn4.x, xn4.y, xn4.z, xn4.w};
                #pragma unroll
                for (int i = 0; i < 4; ++i)
                    *reinterpret_cast<float2*>(&XD[(xc4 + i) * S_DUP + 2 * xrow]) =
                        make_float2(v[i], v[i]);
            }

            // finish rows 4-7: constant indices only
            gate_row(add2(aR[4], SC[SLOT(4, 0)]), add2(aZ[4], SC[SLOT(4, 1)]),
                     add2(aN[4], SC[SLOT(4, 2)]), aX[4], gb, h0r);
            gate_row(add2(aR[5], SC[SLOT(5, 0)]), add2(aZ[5], SC[SLOT(5, 1)]),
                     add2(aN[5], SC[SLOT(5, 2)]), aX[5], gb, h1r);
            gate_row(add2(aR[6], SC[SLOT(6, 0)]), add2(aZ[6], SC[SLOT(6, 1)]),
                     add2(aN[6], SC[SLOT(6, 2)]), aX[6], gb, h2r);
            gate_row(add2(aR[7], SC[SLOT(7, 0)]), add2(aZ[7], SC[SLOT(7, 1)]),
                     add2(aN[7], SC[SLOT(7, 2)]), aX[7], gb, h3r);

            *reinterpret_cast<float2*>(&HD[j0 * S_DUP + 2 * (r0 + 4)])       = make_float2(h0r.x, h0r.x);
            *reinterpret_cast<float2*>(&HD[(j0 + 1) * S_DUP + 2 * (r0 + 4)]) = make_float2(h0r.y, h0r.y);
            *reinterpret_cast<float2*>(&HD[j0 * S_DUP + 2 * (r0 + 5)])       = make_float2(h1r.x, h1r.x);
            *reinterpret_cast<float2*>(&HD[(j0 + 1) * S_DUP + 2 * (r0 + 5)]) = make_float2(h1r.y, h1r.y);
            *reinterpret_cast<float2*>(&HD[j0 * S_DUP + 2 * (r0 + 6)])       = make_float2(h2r.x, h2r.x);
            *reinterpret_cast<float2*>(&HD[(j0 + 1) * S_DUP + 2 * (r0 + 6)]) = make_float2(h2r.y, h2r.y);
            *reinterpret_cast<float2*>(&HD[j0 * S_DUP + 2 * (r0 + 7)])       = make_float2(h3r.x, h3r.x);
            *reinterpret_cast<float2*>(&HD[(j0 + 1) * S_DUP + 2 * (r0 + 7)]) = make_float2(h3r.y, h3r.y);
        }
        __syncthreads();   // HD/XD ready for step t+1
    }

    // final output: this warp's 4 finished rows (grp0: 0-3, grp1: 4-7)
    const int lbase = grp ? 4 : 0;
    float2 hv[4] = {h0r, h1r, h2r, h3r};
    #pragma unroll
    for (int i = 0; i < 4; ++i) {
        int b = bb + r0 + lbase + i;
        if (b < B)
            *reinterpret_cast<float2*>(&out[(size_t)b * H_DIM + j0]) = hv[i];
    }
    #undef SLOT
}

extern "C" void kernel_launch(void* const* d_in, const int* in_sizes, int n_in,
                              void* d_out, int out_size) {
    const float* seq  = (const float*)d_in[0];
    const float* W_ih = (const float*)d_in[1];
    const float* W_hh = (const float*)d_in[2];
    const float* b_ih = (const float*)d_in[3];
    const float* b_hh = (const float*)d_in[4];
    float* out = (float*)d_out;

    const int B = out_size / H_DIM;
    const int T = in_sizes[0] / (B * I_DIM);

    cudaFuncSetAttribute(gru_fwd_kernel,
                         cudaFuncAttributeMaxDynamicSharedMemorySize, SMEM_BYTES);

    const int grid = (B + ROWS_PER_CTA - 1) / ROWS_PER_CTA;
    gru_fwd_kernel<<<grid, THREADS, SMEM_BYTES>>>(seq, W_ih, W_hh, b_ih, b_hh,
                                                  out, B, T);
}

// round 6
// speedup vs baseline: 1.4682x; 1.0523x over previous
#include <cuda_runtime.h>

// GRU: B=4096, T=512, I=32, H=64. out = final hidden (B, H) fp32.
// 128 CTAs x 384 threads. Per "smsp" group s (w&3): 2 h-warps (k-split 32/32
// over the recurrent GEMM) + 1 x-warp computing step t+1's x-projection during
// step t (double-buffered). Exchange + epilogue all smsp-local -> per-smsp
// named barriers. GEMM path: packed fma.rn.f32x2 on duplicated smem operands.

#define THREADS      384
#define ROWS_PER_CTA 32
#define I_DIM        32
#define H_DIM        64
#define G_DIM        192
#define S_DUP        68

#define WS_FLOATS    (96 * G_DIM)        // 18432
#define HD_FLOATS    (H_DIM * S_DUP)     // 4352
#define XD_FLOATS    (I_DIM * S_DUP)     // 2176 (x2 buffers)
#define SC_U64       (2 * 4 * 8 * 3 * 32)  // contrib, smsp, row, acc, lane
#define XP_U64       (2 * 4 * 6 * 3 * 32)  // parity, smsp, row0-5, acc, lane
#define SMEM_BYTES   ((WS_FLOATS + HD_FLOATS + 2 * XD_FLOATS) * 4 + (SC_U64 + XP_U64) * 8)

typedef unsigned long long u64;

__device__ __forceinline__ void fma2(u64& d, u64 a, u64 b) {
    asm("fma.rn.f32x2 %0, %1, %2, %0;" : "+l"(d) : "l"(a), "l"(b));
}
__device__ __forceinline__ u64 add2(u64 a, u64 b) {
    u64 r;
    asm("add.rn.f32x2 %0, %1, %2;" : "=l"(r) : "l"(a), "l"(b));
    return r;
}
__device__ __forceinline__ float2 upk(u64 v) {
    float2 f;
    asm("mov.b64 {%0, %1}, %2;" : "=f"(f.x), "=f"(f.y) : "l"(v));
    return f;
}
__device__ __forceinline__ float tanh_hw(float x) {
    float y;
    asm("tanh.approx.f32 %0, %1;" : "=f"(y) : "f"(x));
    return y;
}
__device__ __forceinline__ float sig_hw(float x) {
    return fmaf(tanh_hw(0.5f * x), 0.5f, 0.5f);
}
__device__ __forceinline__ float tanh_acc(float x) {
    return __fdividef(2.0f, 1.0f + __expf(-2.0f * x)) - 1.0f;
}
__device__ __forceinline__ void barx(int id) {
    asm volatile("bar.sync %0, %1;" :: "r"(id), "r"(96) : "memory");
}

struct GateB { float bR0, bR1, bZ0, bZ1, bIN0, bIN1, bHN0, bHN1; };

__device__ __forceinline__ void gate_row(u64 sR, u64 sZ, u64 sN, u64 sX,
                                         const GateB& b, float2& h01) {
    float2 uR = upk(sR), uZ = upk(sZ), uH = upk(sN), uX = upk(sX);
    float r0g = sig_hw(uR.x + b.bR0);
    float z0g = sig_hw(uZ.x + b.bZ0);
    float n0  = tanh_acc(uX.x + b.bIN0 + r0g * (uH.x + b.bHN0));
    float r1g = sig_hw(uR.y + b.bR1);
    float z1g = sig_hw(uZ.y + b.bZ1);
    float n1  = tanh_acc(uX.y + b.bIN1 + r1g * (uH.y + b.bHN1));
    h01.x = n0 + z0g * (h01.x - n0);
    h01.y = n1 + z1g * (h01.y - n1);
}

// recurrent k-step: acc (aR, aZ, aN), A from HD
#define KSTEP_H(kk)                                                          \
    {                                                                        \
        const float* hk = &HD[(kk) * S_DUP + 2 * r0];                        \
        ulonglong2 A0 = *reinterpret_cast<const ulonglong2*>(hk);            \
        ulonglong2 A1 = *reinterpret_cast<const ulonglong2*>(hk + 4);        \
        ulonglong2 A2 = *reinterpret_cast<const ulonglong2*>(hk + 8);        \
        ulonglong2 A3 = *reinterpret_cast<const ulonglong2*>(hk + 12);       \
        const float* wk = &Ws[(kk) * G_DIM + j0];                            \
        u64 wr = *reinterpret_cast<const u64*>(wk);                          \
        u64 wz = *reinterpret_cast<const u64*>(wk + 64);                     \
        u64 wn = *reinterpret_cast<const u64*>(wk + 128);                    \
        fma2(aR[0], A0.x, wr); fma2(aR[1], A0.y, wr);                        \
        fma2(aR[2], A1.x, wr); fma2(aR[3], A1.y, wr);                        \
        fma2(aR[4], A2.x, wr); fma2(aR[5], A2.y, wr);                        \
        fma2(aR[6], A3.x, wr); fma2(aR[7], A3.y, wr);                        \
        fma2(aZ[0], A0.x, wz); fma2(aZ[1], A0.y, wz);                        \
        fma2(aZ[2], A1.x, wz); fma2(aZ[3], A1.y, wz);                        \
        fma2(aZ[4], A2.x, wz); fma2(aZ[5], A2.y, wz);                        \
        fma2(aZ[6], A3.x, wz); fma2(aZ[7], A3.y, wz);                        \
        fma2(aN[0], A0.x, wn); fma2(aN[1], A0.y, wn);                        \
        fma2(aN[2], A1.x, wn); fma2(aN[3], A1.y, wn);                        \
        fma2(aN[4], A2.x, wn); fma2(aN[5], A2.y, wn);                        \
        fma2(aN[6], A3.x, wn); fma2(aN[7], A3.y, wn);                        \
    }

// x-projection k-step: acc (aR, aZ, aX), A from XDp
#define KSTEP_X(kk, P)                                                       \
    {                                                                        \
        const float* xk = &(P)[(kk) * S_DUP + 2 * r0];                       \
        ulonglong2 A0 = *reinterpret_cast<const ulonglong2*>(xk);            \
        ulonglong2 A1 = *reinterpret_cast<const ulonglong2*>(xk + 4);        \
        ulonglong2 A2 = *reinterpret_cast<const ulonglong2*>(xk + 8);        \
        ulonglong2 A3 = *reinterpret_cast<const ulonglong2*>(xk + 12);       \
        const float* wk = &Ws[(H_DIM + (kk)) * G_DIM + j0];                  \
        u64 wr = *reinterpret_cast<const u64*>(wk);                          \
        u64 wz = *reinterpret_cast<const u64*>(wk + 64);                     \
        u64 wn = *reinterpret_cast<const u64*>(wk + 128);                    \
        fma2(aR[0], A0.x, wr); fma2(aR[1], A0.y, wr);                        \
        fma2(aR[2], A1.x, wr); fma2(aR[3], A1.y, wr);                        \
        fma2(aR[4], A2.x, wr); fma2(aR[5], A2.y, wr);                        \
        fma2(aR[6], A3.x, wr); fma2(aR[7], A3.y, wr);                        \
        fma2(aZ[0], A0.x, wz); fma2(aZ[1], A0.y, wz);                        \
        fma2(aZ[2], A1.x, wz); fma2(aZ[3], A1.y, wz);                        \
        fma2(aZ[4], A2.x, wz); fma2(aZ[5], A2.y, wz);                        \
        fma2(aZ[6], A3.x, wz); fma2(aZ[7], A3.y, wz);                        \
        fma2(aX[0], A0.x, wn); fma2(aX[1], A0.y, wn);                        \
        fma2(aX[2], A1.x, wn); fma2(aX[3], A1.y, wn);                        \
        fma2(aX[4], A2.x, wn); fma2(aX[5], A2.y, wn);                        \
        fma2(aX[6], A3.x, wn); fma2(aX[7], A3.y, wn);                        \
    }

#define SCI(g, l, a)  (((((g) * 4 + smsp) * 8 + (l)) * 3 + (a)) * 32 + c)
#define XPI(p, l, a)  (((((p) * 4 + smsp) * 6 + (l)) * 3 + (a)) * 32 + c)

#define HDWR(gr, hv)                                                                \
    *reinterpret_cast<float2*>(&HD[j0 * S_DUP + 2 * (gr)])       = make_float2((hv).x, (hv).x); \
    *reinterpret_cast<float2*>(&HD[(j0 + 1) * S_DUP + 2 * (gr)]) = make_float2((hv).y, (hv).y);

__global__ void __launch_bounds__(THREADS, 1)
gru_fwd_kernel(const float* __restrict__ seq,
               const float* __restrict__ W_ih,
               const float* __restrict__ W_hh,
               const float* __restrict__ b_ih,
               const float* __restrict__ b_hh,
               float* __restrict__ out,
               int B, int T)
{
    extern __shared__ float sm[];
    float* Ws = sm;
    float* HD = sm + WS_FLOATS;
    float* XD = HD + HD_FLOATS;                    // 2 buffers
    u64*   SCb = (u64*)(XD + 2 * XD_FLOATS);
    u64*   XPb = SCb + SC_U64;

    const int tid  = threadIdx.x;
    const int w    = tid >> 5;
    const int c    = tid & 31;
    const int smsp = (w < 8) ? (w & 3) : (w - 8);
    const int grp  = w >> 2;                        // 0,1: h-warps, 2: x-warp
    const int bb   = blockIdx.x * ROWS_PER_CTA;
    const int r0   = smsp * 8;
    const int j0   = 2 * c;
    const int barid = 1 + smsp;

    // ---- one-time init ----
    for (int idx = tid; idx < G_DIM * H_DIM; idx += THREADS) {
        int gg = idx / H_DIM, k = idx % H_DIM;
        Ws[k * G_DIM + gg] = W_hh[idx];
    }
    for (int idx = tid; idx < G_DIM * I_DIM; idx += THREADS) {
        int gg = idx / I_DIM, i = idx % I_DIM;
        Ws[(H_DIM + i) * G_DIM + gg] = W_ih[idx];
    }
    for (int idx = tid; idx < HD_FLOATS; idx += THREADS) HD[idx] = 0.0f;

    GateB gb;
    gb.bR0  = b_ih[j0]      + b_hh[j0];
    gb.bR1  = b_ih[j0 + 1]  + b_hh[j0 + 1];
    gb.bZ0  = b_ih[64 + j0] + b_hh[64 + j0];
    gb.bZ1  = b_ih[65 + j0] + b_hh[65 + j0];
    gb.bIN0 = b_ih[128 + j0]; gb.bIN1 = b_ih[129 + j0];
    gb.bHN0 = b_hh[128 + j0]; gb.bHN1 = b_hh[129 + j0];

    // stager role (h-warps only): q in [0,64) within smsp; 8 threads per row
    const int q     = (grp == 1 ? 32 : 0) + c;      // valid for w<8
    const int srow  = r0 + (q >> 3);                // CTA-local row
    const int scol4 = (q & 7) * 4;
    const float* xptr = seq + (size_t)(bb + srow) * T * I_DIM + scol4;

    float2 h0r = make_float2(0.f, 0.f), h1r = h0r, h2r = h0r;
    u64 pR6 = 0, pZ6 = 0, pX6 = 0, pR7 = 0, pZ7 = 0, pX7 = 0;   // x-warp prev

    // prologue: stage x(0) -> XD[0], x(1) -> XD[1]
    if (w < 8) {
        float4 v0 = *reinterpret_cast<const float4*>(xptr);
        #pragma unroll
        for (int i = 0; i < 4; ++i) {
            float vv = (&v0.x)[i];
            *reinterpret_cast<float2*>(&XD[(scol4 + i) * S_DUP + 2 * srow]) =
                make_float2(vv, vv);
        }
        if (T > 1) {
            float4 v1 = *reinterpret_cast<const float4*>(xptr + I_DIM);
            #pragma unroll
            for (int i = 0; i < 4; ++i) {
                float vv = (&v1.x)[i];
                *reinterpret_cast<float2*>(&XD[XD_FLOATS + (scol4 + i) * S_DUP + 2 * srow]) =
                    make_float2(vv, vv);
            }
        }
    }
    __syncthreads();

    // prologue: x-warps compute XP(0) from XD[0]
    if (w >= 8) {
        u64 aR[8], aZ[8], aX[8];
        #pragma unroll
        for (int i = 0; i < 8; ++i) { aR[i] = 0; aZ[i] = 0; aX[i] = 0; }
        const float* XDp = XD;
        #pragma unroll 8
        for (int k = 0; k < I_DIM; ++k) KSTEP_X(k, XDp)
        #pragma unroll
        for (int l = 0; l < 6; ++l) {
            XPb[XPI(0, l, 0)] = aR[l];
            XPb[XPI(0, l, 1)] = aZ[l];
            XPb[XPI(0, l, 2)] = aX[l];
        }
        pR6 = aR[6]; pZ6 = aZ[6]; pX6 = aX[6];
        pR7 = aR[7]; pZ7 = aZ[7]; pX7 = aX[7];
    }
    __syncthreads();

    for (int t = 0; t < T; ++t) {
        const int par  = t & 1;          // XP parity for this step's epilogue
        const int par2 = (t + 1) & 1;    // XP parity written by x-warp

        if (w < 8) {
            // x(t+2) prefetch
            float4 xn4 = make_float4(0.f, 0.f, 0.f, 0.f);
            if (t + 2 < T)
                xn4 = *reinterpret_cast<const float4*>(xptr + (size_t)(t + 2) * I_DIM);

            u64 aR[8], aZ[8], aN[8];
            #pragma unroll
            for (int i = 0; i < 8; ++i) { aR[i] = 0; aZ[i] = 0; aN[i] = 0; }
            const int koff = grp * 32;
            #pragma unroll 8
            for (int k = 0; k < 32; ++k) KSTEP_H(koff + k)

            if (grp == 0) {
                #pragma unroll
                for (int l = 3; l < 8; ++l) {
                    SCb[SCI(0, l, 0)] = aR[l];
                    SCb[SCI(0, l, 1)] = aZ[l];
                    SCb[SCI(0, l, 2)] = aN[l];
                }
            } else {
                SCb[SCI(1, 0, 0)] = aR[0]; SCb[SCI(1, 0, 1)] = aZ[0]; SCb[SCI(1, 0, 2)] = aN[0];
                SCb[SCI(1, 1, 0)] = aR[1]; SCb[SCI(1, 1, 1)] = aZ[1]; SCb[SCI(1, 1, 2)] = aN[1];
                SCb[SCI(1, 2, 0)] = aR[2]; SCb[SCI(1, 2, 1)] = aZ[2]; SCb[SCI(1, 2, 2)] = aN[2];
                SCb[SCI(1, 6, 0)] = aR[6]; SCb[SCI(1, 6, 1)] = aZ[6]; SCb[SCI(1, 6, 2)] = aN[6];
                SCb[SCI(1, 7, 0)] = aR[7]; SCb[SCI(1, 7, 1)] = aZ[7]; SCb[SCI(1, 7, 2)] = aN[7];
            }
            barx(barid);

            // stage x(t+2) into XD[t&1]
            if (t + 2 < T) {
                #pragma unroll
                for (int i = 0; i < 4; ++i) {
                    float vv = (&xn4.x)[i];
                    *reinterpret_cast<float2*>(&XD[par * XD_FLOATS + (scol4 + i) * S_DUP + 2 * srow]) =
                        make_float2(vv, vv);
                }
            }

            if (grp == 0) {
                // finish rows 0-2: own + SC(contrib 1) + XP
                gate_row(add2(add2(aR[0], SCb[SCI(1, 0, 0)]), XPb[XPI(par, 0, 0)]),
                         add2(add2(aZ[0], SCb[SCI(1, 0, 1)]), XPb[XPI(par, 0, 1)]),
                         add2(aN[0], SCb[SCI(1, 0, 2)]),
                         XPb[XPI(par, 0, 2)], gb, h0r);
                gate_row(add2(add2(aR[1], SCb[SCI(1, 1, 0)]), XPb[XPI(par, 1, 0)]),
                         add2(add2(aZ[1], SCb[SCI(1, 1, 1)]), XPb[XPI(par, 1, 1)]),
                         add2(aN[1], SCb[SCI(1, 1, 2)]),
                         XPb[XPI(par, 1, 2)], gb, h1r);
                gate_row(add2(add2(aR[2], SCb[SCI(1, 2, 0)]), XPb[XPI(par, 2, 0)]),
                         add2(add2(aZ[2], SCb[SCI(1, 2, 1)]), XPb[XPI(par, 2, 1)]),
                         add2(aN[2], SCb[SCI(1, 2, 2)]),
                         XPb[XPI(par, 2, 2)], gb, h2r);
                HDWR(r0 + 0, h0r)
                HDWR(r0 + 1, h1r)
                HDWR(r0 + 2, h2r)
            } else {
                // finish rows 3-5: own + SC(contrib 0) + XP
                gate_row(add2(add2(aR[3], SCb[SCI(0, 3, 0)]), XPb[XPI(par, 3, 0)]),
                         add2(add2(aZ[3], SCb[SCI(0, 3, 1)]), XPb[XPI(par, 3, 1)]),
                         add2(aN[3], SCb[SCI(0, 3, 2)]),
                         XPb[XPI(par, 3, 2)], gb, h0r);
                gate_row(add2(add2(aR[4], SCb[SCI(0, 4, 0)]), XPb[XPI(par, 4, 0)]),
                         add2(add2(aZ[4], SCb[SCI(0, 4, 1)]), XPb[XPI(par, 4, 1)]),
                         add2(aN[4], SCb[SCI(0, 4, 2)]),
                         XPb[XPI(par, 4, 2)], gb, h1r);
                gate_row(add2(add2(aR[5], SCb[SCI(0, 5, 0)]), XPb[XPI(par, 5, 0)]),
                         add2(add2(aZ[5], SCb[SCI(0, 5, 1)]), XPb[XPI(par, 5, 1)]),
                         add2(aN[5], SCb[SCI(0, 5, 2)]),
                         XPb[XPI(par, 5, 2)], gb, h2r);
                HDWR(r0 + 3, h0r)
                HDWR(r0 + 4, h1r)
                HDWR(r0 + 5, h2r)
            }
        } else {
            // x-warp: compute XP(t+1)
            u64 aR[8], aZ[8], aX[8];
            #pragma unroll
            for (int i = 0; i < 8; ++i) { aR[i] = 0; aZ[i] = 0; aX[i] = 0; }
            if (t + 1 < T) {
                const float* XDp = XD + par2 * XD_FLOATS;
                #pragma unroll 8
                for (int k = 0; k < I_DIM; ++k) KSTEP_X(k, XDp)
                #pragma unroll
                for (int l = 0; l < 6; ++l) {
                    XPb[XPI(par2, l, 0)] = aR[l];
                    XPb[XPI(par2, l, 1)] = aZ[l];
                    XPb[XPI(par2, l, 2)] = aX[l];
                }
            }
            barx(barid);

            // finish rows 6-7: SC(0) + SC(1) + prev XP (regs)
            gate_row(add2(add2(SCb[SCI(0, 6, 0)], SCb[SCI(1, 6, 0)]), pR6),
                     add2(add2(SCb[SCI(0, 6, 1)], SCb[SCI(1, 6, 1)]), pZ6),
                     add2(SCb[SCI(0, 6, 2)], SCb[SCI(1, 6, 2)]),
                     pX6, gb, h0r);
            gate_row(add2(add2(SCb[SCI(0, 7, 0)], SCb[SCI(1, 7, 0)]), pR7),
                     add2(add2(SCb[SCI(0, 7, 1)], SCb[SCI(1, 7, 1)]), pZ7),
                     add2(SCb[SCI(0, 7, 2)], SCb[SCI(1, 7, 2)]),
                     pX7, gb, h1r);
            HDWR(r0 + 6, h0r)
            HDWR(r0 + 7, h1r)

            pR6 = aR[6]; pZ6 = aZ[6]; pX6 = aX[6];
            pR7 = aR[7]; pZ7 = aZ[7]; pX7 = aX[7];
        }
        barx(barid);
    }

    // ---- final output ----
    if (w < 8) {
        const int base = (grp == 0) ? 0 : 3;
        int b0 = bb + r0 + base;
        *reinterpret_cast<float2*>(&out[(size_t)(b0 + 0) * H_DIM + j0]) = h0r;
        *reinterpret_cast<float2*>(&out[(size_t)(b0 + 1) * H_DIM + j0]) = h1r;
        *reinterpret_cast<float2*>(&out[(size_t)(b0 + 2) * H_DIM + j0]) = h2r;
    } else {
        int b0 = bb + r0 + 6;
        *reinterpret_cast<float2*>(&out[(size_t)(b0 + 0) * H_DIM + j0]) = h0r;
        *reinterpret_cast<float2*>(&out[(size_t)(b0 + 1) * H_DIM + j0]) = h1r;
    }
}

extern "C" void kernel_launch(void* const* d_in, const int* in_sizes, int n_in,
                              void* d_out, int out_size) {
    const float* seq  = (const float*)d_in[0];
    const float* W_ih = (const float*)d_in[1];
    const float* W_hh = (const float*)d_in[2];
    const float* b_ih = (const float*)d_in[3];
    const float* b_hh = (const float*)d_in[4];
    float* out = (float*)d_out;

    const int B = out_size / H_DIM;
    const int T = in_sizes[0] / (B * I_DIM);

    cudaFuncSetAttribute(gru_fwd_kernel,
                         cudaFuncAttributeMaxDynamicSharedMemorySize, SMEM_BYTES);

    const int grid = (B + ROWS_PER_CTA - 1) / ROWS_PER_CTA;
    gru_fwd_kernel<<<grid, THREADS, SMEM_BYTES>>>(seq, W_ih, W_hh, b_ih, b_hh,
                                                  out, B, T);
}